// round 15
// baseline (speedup 1.0000x reference)
#include <cuda_runtime.h>
#include <cuda_bf16.h>
#include <cuda_fp16.h>
#include <math.h>
#include <float.h>
#include <stdint.h>

#define B_   2
#define L_   2048
#define E_   768
#define H_   12
#define D_   64
#define M_   (B_*L_)
#define NQKV (3*E_)
#define KDIM 768
#define BH_  (B_*H_)

// Scratch (__device__ globals per allocation rules)
__device__ __nv_bfloat16 g_xh[M_*KDIM],    g_xl[M_*KDIM];
__device__ __nv_bfloat16 g_wqh[NQKV*KDIM], g_wql[NQKV*KDIM];
__device__ __nv_bfloat16 g_woh[E_*KDIM],   g_wol[E_*KDIM];
__device__ __nv_bfloat16 g_qh[BH_*L_*D_],  g_ql[BH_*L_*D_];
__device__ __nv_bfloat16 g_kh[BH_*L_*D_],  g_kl[BH_*L_*D_];
__device__ __half        g_vh[BH_*L_*D_];                    // [bh][l][d], fp16 row-major
__device__ __nv_bfloat16 g_ath[M_*E_],     g_atl[M_*E_];
__device__ float g_qsq[BH_*L_], g_ksq[BH_*L_];               // g_ksq has +eps folded

__device__ __forceinline__ uint32_t smem_u32(const void* p) {
    uint32_t a;
    asm("{ .reg .u64 t; cvta.to.shared.u64 t, %1; cvt.u32.u64 %0, t; }" : "=r"(a) : "l"(p));
    return a;
}
__device__ __forceinline__ float frcp(float x) {
    float r;
    asm("rcp.approx.f32 %0, %1;" : "=f"(r) : "f"(x));
    return r;
}
__device__ __forceinline__ void mma_bf16(float c[4], const uint32_t a[4],
                                         uint32_t b0, uint32_t b1) {
    asm volatile(
        "mma.sync.aligned.m16n8k16.row.col.f32.bf16.bf16.f32 "
        "{%0,%1,%2,%3}, {%4,%5,%6,%7}, {%8,%9}, {%0,%1,%2,%3};"
        : "+f"(c[0]), "+f"(c[1]), "+f"(c[2]), "+f"(c[3])
        : "r"(a[0]), "r"(a[1]), "r"(a[2]), "r"(a[3]), "r"(b0), "r"(b1));
}
__device__ __forceinline__ void mma_fp16(float c[4], const uint32_t a[4],
                                         uint32_t b0, uint32_t b1) {
    asm volatile(
        "mma.sync.aligned.m16n8k16.row.col.f32.f16.f16.f32 "
        "{%0,%1,%2,%3}, {%4,%5,%6,%7}, {%8,%9}, {%0,%1,%2,%3};"
        : "+f"(c[0]), "+f"(c[1]), "+f"(c[2]), "+f"(c[3])
        : "r"(a[0]), "r"(a[1]), "r"(a[2]), "r"(a[3]), "r"(b0), "r"(b1));
}
__device__ __forceinline__ void ldsm4(uint32_t r[4], uint32_t addr) {
    asm volatile("ldmatrix.sync.aligned.m8n8.x4.shared.b16 {%0,%1,%2,%3}, [%4];"
                 : "=r"(r[0]), "=r"(r[1]), "=r"(r[2]), "=r"(r[3]) : "r"(addr));
}
__device__ __forceinline__ void ldsm4t(uint32_t r[4], uint32_t addr) {
    asm volatile("ldmatrix.sync.aligned.m8n8.x4.trans.shared.b16 {%0,%1,%2,%3}, [%4];"
                 : "=r"(r[0]), "=r"(r[1]), "=r"(r[2]), "=r"(r[3]) : "r"(addr));
}
__device__ __forceinline__ void cpasync16(uint32_t dst, const void* src) {
    size_t g = __cvta_generic_to_global(src);
    asm volatile("cp.async.ca.shared.global [%0], [%1], 16;" :: "r"(dst), "l"(g));
}
#define CP_COMMIT() asm volatile("cp.async.commit_group;" ::: "memory")
#define CP_WAIT0()  asm volatile("cp.async.wait_group 0;" ::: "memory")

__device__ __forceinline__ void split_pair(float x0, float x1,
                                           uint32_t& hp, uint32_t& lp) {
    __nv_bfloat16 h0 = __float2bfloat16(x0), h1 = __float2bfloat16(x1);
    hp = ((uint32_t)__bfloat16_as_ushort(h1) << 16) | __bfloat16_as_ushort(h0);
    __nv_bfloat16 l0 = __float2bfloat16(x0 - __bfloat162float(h0));
    __nv_bfloat16 l1 = __float2bfloat16(x1 - __bfloat162float(h1));
    lp = ((uint32_t)__bfloat16_as_ushort(l1) << 16) | __bfloat16_as_ushort(l0);
}
__device__ __forceinline__ uint32_t pack_h2(float x0, float x1) {
    __half2 h = __floats2half2_rn(x0, x1);
    return *reinterpret_cast<uint32_t*>(&h);
}

// ---------------- merged preprocessing (one launch) ----------------
#define PRE_CONV 3072
#define PRE_WQ   1728
#define PRE_WO   576

__global__ __launch_bounds__(256) void preproc(const float* __restrict__ x,
                                               const float* __restrict__ Wqkv,
                                               const float* __restrict__ Wout) {
    int bid = blockIdx.x;
    if (bid < PRE_CONV) {
        int i = (bid * 256 + threadIdx.x) * 4;
        float4 v = *(const float4*)(x + i);
        uint32_t h0, l0, h1, l1;
        split_pair(v.x, v.y, h0, l0);
        split_pair(v.z, v.w, h1, l1);
        *reinterpret_cast<uint2*>(g_xh + i) = make_uint2(h0, h1);
        *reinterpret_cast<uint2*>(g_xl + i) = make_uint2(l0, l1);
        return;
    }
    __shared__ float tile[32][33];
    const float* in;
    __nv_bfloat16 *oh, *ol;
    int N, idx;
    if (bid < PRE_CONV + PRE_WQ) {
        idx = bid - PRE_CONV; N = NQKV; in = Wqkv; oh = g_wqh; ol = g_wql;
    } else {
        idx = bid - PRE_CONV - PRE_WQ; N = E_; in = Wout; oh = g_woh; ol = g_wol;
    }
    int nblk = N / 32;
    int n0 = (idx % nblk) * 32, k0 = (idx / nblk) * 32;
    int tx = threadIdx.x & 31, ty = threadIdx.x >> 5;
    #pragma unroll
    for (int i = 0; i < 32; i += 8)
        tile[ty + i][tx] = in[(size_t)(k0 + ty + i) * N + n0 + tx];
    __syncthreads();
    #pragma unroll
    for (int i = 0; i < 32; i += 8) {
        float v = tile[tx][ty + i];
        __nv_bfloat16 h = __float2bfloat16(v);
        size_t o = (size_t)(n0 + ty + i) * KDIM + k0 + tx;
        oh[o] = h;
        ol[o] = __float2bfloat16(v - __bfloat162float(h));
    }
}

__global__ __launch_bounds__(256) void sqnorm_kernel() {
    int i = blockIdx.x * 256 + threadIdx.x;
    const uint32_t* qh = (const uint32_t*)g_qh + (size_t)i * 32;
    const uint32_t* ql = (const uint32_t*)g_ql + (size_t)i * 32;
    const uint32_t* kh = (const uint32_t*)g_kh + (size_t)i * 32;
    const uint32_t* kl = (const uint32_t*)g_kl + (size_t)i * 32;
    float sq = 0.f, sk = 0.f;
    #pragma unroll
    for (int j = 0; j < 32; j++) {
        uint32_t uh = qh[j], ul = ql[j];
        float2 fh = __bfloat1622float2(*reinterpret_cast<__nv_bfloat162*>(&uh));
        float2 fl = __bfloat1622float2(*reinterpret_cast<__nv_bfloat162*>(&ul));
        float v0 = fh.x + fl.x, v1 = fh.y + fl.y;
        sq += v0 * v0 + v1 * v1;
        uh = kh[j]; ul = kl[j];
        fh = __bfloat1622float2(*reinterpret_cast<__nv_bfloat162*>(&uh));
        fl = __bfloat1622float2(*reinterpret_cast<__nv_bfloat162*>(&ul));
        v0 = fh.x + fl.x; v1 = fh.y + fl.y;
        sk += v0 * v0 + v1 * v1;
    }
    g_qsq[i] = sq;
    g_ksq[i] = sk + 1e-6f;
}

// ---------------- bf16-split tensor-core GEMM ----------------
#define GBUF 73728
#define GEMM_SMEM (2*GBUF)

__global__ __launch_bounds__(256, 1) void gemm_bf16(
    const __nv_bfloat16* __restrict__ Ah, const __nv_bfloat16* __restrict__ Al,
    const __nv_bfloat16* __restrict__ Bh, const __nv_bfloat16* __restrict__ Bl,
    const float* __restrict__ bias, float* __restrict__ Cout, int mode) {
    extern __shared__ char smraw[];
    uint32_t sbase = smem_u32(smraw);
    const int t = threadIdx.x, lane = t & 31, w = t >> 5;
    const int wm = w >> 2, wn = w & 3;
    const int m0 = blockIdx.y * 128, n0 = blockIdx.x * 128;

    float acc[4][4][4];
    #pragma unroll
    for (int a = 0; a < 4; a++)
        #pragma unroll
        for (int b = 0; b < 4; b++)
            #pragma unroll
            for (int c = 0; c < 4; c++) acc[a][b][c] = 0.f;

    auto stage = [&](int c, int buf) {
        uint32_t sb = sbase + buf * GBUF;
        #pragma unroll
        for (int i = 0; i < 4; i++) {
            int idx = t + i * 256;
            int row = idx >> 3, c16 = idx & 7;
            size_t go = ((size_t)(m0 + row) * KDIM + c * 64 + c16 * 8) * 2;
            uint32_t so = row * 144 + c16 * 16;
            cpasync16(sb + so,         (const char*)Ah + go);
            cpasync16(sb + 18432 + so, (const char*)Al + go);
            size_t bo = ((size_t)(n0 + row) * KDIM + c * 64 + c16 * 8) * 2;
            cpasync16(sb + 36864 + so, (const char*)Bh + bo);
            cpasync16(sb + 55296 + so, (const char*)Bl + bo);
        }
    };

    stage(0, 0); CP_COMMIT();
    const int arow_l = ((lane >> 3) & 1) * 8 + (lane & 7);
    const int akc_h  = ((lane >> 4) & 1) * 8;
    const int brow_l = ((lane >> 4) & 1) * 8 + (lane & 7);
    const int bkc_h  = ((lane >> 3) & 1) * 8;

    for (int c = 0; c < 12; c++) {
        CP_WAIT0();
        __syncthreads();
        if (c < 11) { stage(c + 1, (c + 1) & 1); CP_COMMIT(); }
        uint32_t sb = sbase + (c & 1) * GBUF;
        #pragma unroll
        for (int ks = 0; ks < 4; ks++) {
            uint32_t aH[4][4], aL[4][4], bH[4][2], bL[4][2];
            #pragma unroll
            for (int mi = 0; mi < 4; mi++) {
                uint32_t ro = (wm * 64 + mi * 16 + arow_l) * 144 + (ks * 16 + akc_h) * 2;
                ldsm4(aH[mi], sb + ro);
                ldsm4(aL[mi], sb + 18432 + ro);
            }
            #pragma unroll
            for (int np = 0; np < 2; np++) {
                uint32_t r[4];
                uint32_t ro = (wn * 32 + np * 16 + brow_l) * 144 + (ks * 16 + bkc_h) * 2;
                ldsm4(r, sb + 36864 + ro);
                bH[np*2][0] = r[0]; bH[np*2][1] = r[1];
                bH[np*2+1][0] = r[2]; bH[np*2+1][1] = r[3];
                ldsm4(r, sb + 55296 + ro);
                bL[np*2][0] = r[0]; bL[np*2][1] = r[1];
                bL[np*2+1][0] = r[2]; bL[np*2+1][1] = r[3];
            }
            #pragma unroll
            for (int mi = 0; mi < 4; mi++)
                #pragma unroll
                for (int ni = 0; ni < 4; ni++) {
                    mma_bf16(acc[mi][ni], aH[mi], bH[ni][0], bH[ni][1]);
                    mma_bf16(acc[mi][ni], aH[mi], bL[ni][0], bL[ni][1]);
                    mma_bf16(acc[mi][ni], aL[mi], bH[ni][0], bH[ni][1]);
                }
        }
    }

    const int cb = (lane & 3) * 2;
    #pragma unroll
    for (int mi = 0; mi < 4; mi++) {
        int r0 = m0 + wm * 64 + mi * 16 + (lane >> 2);
        #pragma unroll
        for (int ni = 0; ni < 4; ni++) {
            int ncol = n0 + wn * 32 + ni * 8 + cb;
            float b0 = bias[ncol], b1 = bias[ncol + 1];
            float v[2][2] = {{acc[mi][ni][0] + b0, acc[mi][ni][1] + b1},
                             {acc[mi][ni][2] + b0, acc[mi][ni][3] + b1}};
            if (mode == 1) {
                *(float2*)(Cout + (size_t)r0 * E_ + ncol)       = make_float2(v[0][0], v[0][1]);
                *(float2*)(Cout + (size_t)(r0 + 8) * E_ + ncol) = make_float2(v[1][0], v[1][1]);
            } else {
                int s = ncol / E_;
                int rem = ncol - s * E_;
                int hh = rem >> 6, dd = rem & 63;
                #pragma unroll
                for (int rr = 0; rr < 2; rr++) {
                    int row = r0 + rr * 8;
                    int bb = row >> 11, l = row & (L_ - 1);
                    int bh = bb * H_ + hh;
                    size_t idx = ((size_t)bh * L_ + l) * D_ + dd;
                    if (s < 2) {
                        uint32_t hp, lp;
                        split_pair(v[rr][0], v[rr][1], hp, lp);
                        *(uint32_t*)((s ? g_kh : g_qh) + idx) = hp;
                        *(uint32_t*)((s ? g_kl : g_ql) + idx) = lp;
                    } else {
                        *(uint32_t*)(g_vh + idx) = pack_h2(v[rr][0], v[rr][1]);  // coalesced
                    }
                }
            }
        }
    }
}

// ---------------- fused Yat attention: V row-major + ldsm.trans, exp/PV interleave ----------------
#define AQB   36864
#define ABUF2 28160
#define ATTN_SMEM (AQB + 2*ABUF2)   // 93184

__global__ __launch_bounds__(256, 2) void yat_attn_mma(const int* __restrict__ mask) {
    extern __shared__ char smraw[];
    uint32_t sbase = smem_u32(smraw);
    const int t = threadIdx.x, lane = t & 31, w = t >> 5;
    const int bh = blockIdx.y, b = bh / H_, hh = bh - b * H_;
    const int qt0 = blockIdx.x * 128;
    const int cb = (lane & 3) * 2;
    const int qrow0 = qt0 + w * 16 + (lane >> 2);
    const int qrow1 = qrow0 + 8;

    const int arow_l = ((lane >> 3) & 1) * 8 + (lane & 7);
    const int akc_h  = ((lane >> 4) & 1) * 8;
    const int krow_l = ((lane >> 4) & 1) * 8 + (lane & 7);
    const int kkc_h  = ((lane >> 3) & 1) * 8;

    // Stage Q tile (hi/lo) into smem once
    #pragma unroll
    for (int i = 0; i < 4; i++) {
        int idx = t + i * 256;
        int row = idx >> 3, c16 = idx & 7;
        size_t go = ((size_t)(bh * L_ + qt0 + row) * 64 + c16 * 8) * 2;
        uint32_t so = row * 144 + c16 * 16;
        cpasync16(sbase + so,         (const char*)g_qh + go);
        cpasync16(sbase + 18432 + so, (const char*)g_ql + go);
    }

    // Staging constants (2 rows per thread); K and V share [bh][l][d] indexing
    const int srow0 = t >> 3,   sc16 = t & 7;
    const int srow1 = srow0 + 32;
    const uint32_t so0 = srow0 * 144 + sc16 * 16;
    const uint32_t so1 = srow1 * 144 + sc16 * 16;
    const size_t goff0 = ((size_t)(bh * L_ + srow0) * 64 + sc16 * 8) * 2;
    const size_t goff1 = ((size_t)(bh * L_ + srow1) * 64 + sc16 * 8) * 2;

    auto stage = [&](int it, int buf) {
        uint32_t sb = sbase + AQB + buf * ABUF2;
        size_t ko = (size_t)it * 64 * 64 * 2;   // 8192 B per tile
        cpasync16(sb + so0,         (const char*)g_kh + goff0 + ko);
        cpasync16(sb + so1,         (const char*)g_kh + goff1 + ko);
        cpasync16(sb + 9216 + so0,  (const char*)g_kl + goff0 + ko);
        cpasync16(sb + 9216 + so1,  (const char*)g_kl + goff1 + ko);
        cpasync16(sb + 18432 + so0, (const char*)g_vh + goff0 + ko);
        cpasync16(sb + 18432 + so1, (const char*)g_vh + goff1 + ko);
        if (t < 64) {
            float2* kq = (float2*)(smraw + AQB + buf * ABUF2 + 27648);
            int kv = it * 64 + t;
            kq[t] = make_float2(g_ksq[bh * L_ + kv],
                                mask[b * L_ + kv] ? 0.f : -FLT_MAX);
        }
    };

    stage(0, 0); CP_COMMIT();

    const float qs0 = g_qsq[bh * L_ + qrow0];
    const float qs1 = g_qsq[bh * L_ + qrow1];

    float mi0 = -FLT_MAX, mi1 = -FLT_MAX, li0 = 0.f, li1 = 0.f;
    float O[8][4];
    #pragma unroll
    for (int i = 0; i < 8; i++)
        #pragma unroll
        for (int j = 0; j < 4; j++) O[i][j] = 0.f;

    for (int it = 0; it < 32; it++) {
        CP_WAIT0();
        __syncthreads();
        if (it < 31) { stage(it + 1, (it + 1) & 1); CP_COMMIT(); }
        uint32_t sb = sbase + AQB + (it & 1) * ABUF2;
        const float2* kqpen = (const float2*)(smraw + AQB + (it & 1) * ABUF2 + 27648);

        float S[8][4];
        #pragma unroll
        for (int i = 0; i < 8; i++)
            #pragma unroll
            for (int j = 0; j < 4; j++) S[i][j] = 0.f;
        float rm0 = -FLT_MAX, rm1 = -FLT_MAX;

        auto transform_pair = [&](int pp) {
            #pragma unroll
            for (int jj = 0; jj < 2; jj++) {
                int j = 2 * pp + jj;
                float2 kp0 = kqpen[j * 8 + cb];
                float2 kp1 = kqpen[j * 8 + cb + 1];
                float d, sc;
                d = S[j][0];
                sc = fmaf(d * d, frcp(fmaf(-2.f, d, qs0 + kp0.x)), kp0.y);
                S[j][0] = sc; rm0 = fmaxf(rm0, sc);
                d = S[j][1];
                sc = fmaf(d * d, frcp(fmaf(-2.f, d, qs0 + kp1.x)), kp1.y);
                S[j][1] = sc; rm0 = fmaxf(rm0, sc);
                d = S[j][2];
                sc = fmaf(d * d, frcp(fmaf(-2.f, d, qs1 + kp0.x)), kp0.y);
                S[j][2] = sc; rm1 = fmaxf(rm1, sc);
                d = S[j][3];
                sc = fmaf(d * d, frcp(fmaf(-2.f, d, qs1 + kp1.x)), kp1.y);
                S[j][3] = sc; rm1 = fmaxf(rm1, sc);
            }
        };

        uint32_t qah[4][4], qal[4][4];
        #pragma unroll
        for (int ks = 0; ks < 4; ks++) {
            uint32_t qro = (w * 16 + arow_l) * 144 + (ks * 16 + akc_h) * 2;
            ldsm4(qah[ks], sbase + qro);
            ldsm4(qal[ks], sbase + 18432 + qro);
        }

        #pragma unroll
        for (int p = 0; p < 4; p++) {
            #pragma unroll
            for (int ks = 0; ks < 4; ks++) {
                uint32_t rh[4], rl[4];
                uint32_t ro = (p * 16 + krow_l) * 144 + (ks * 16 + kkc_h) * 2;
                ldsm4(rh, sb + ro);
                ldsm4(rl, sb + 9216 + ro);
                mma_bf16(S[2*p],   qah[ks], rh[0], rh[1]);
                mma_bf16(S[2*p],   qah[ks], rl[0], rl[1]);
                mma_bf16(S[2*p],   qal[ks], rh[0], rh[1]);
                mma_bf16(S[2*p+1], qah[ks], rh[2], rh[3]);
                mma_bf16(S[2*p+1], qah[ks], rl[2], rl[3]);
                mma_bf16(S[2*p+1], qal[ks], rh[2], rh[3]);
            }
            if (p > 0) transform_pair(p - 1);
        }
        transform_pair(3);

        rm0 = fmaxf(rm0, __shfl_xor_sync(0xffffffffu, rm0, 1));
        rm0 = fmaxf(rm0, __shfl_xor_sync(0xffffffffu, rm0, 2));
        rm1 = fmaxf(rm1, __shfl_xor_sync(0xffffffffu, rm1, 1));
        rm1 = fmaxf(rm1, __shfl_xor_sync(0xffffffffu, rm1, 2));

        float mn0 = fmaxf(mi0, rm0), mn1 = fmaxf(mi1, rm1);
        float sc0 = __expf(mi0 - mn0), sc1 = __expf(mi1 - mn1);
        #pragma unroll
        for (int j = 0; j < 8; j++) {
            O[j][0] *= sc0; O[j][1] *= sc0;
            O[j][2] *= sc1; O[j][3] *= sc1;
        }

        // exp+pack pair p, then PV MMAs of pair p (fills tensor pipe during exp)
        float rs0 = 0.f, rs1 = 0.f;
        #pragma unroll
        for (int p = 0; p < 4; p++) {
            uint32_t ap[4];
            #pragma unroll
            for (int jj = 0; jj < 2; jj++) {
                int j = 2 * p + jj;
                float p0 = __expf(S[j][0] - mn0);
                float p1 = __expf(S[j][1] - mn0);
                float p2 = __expf(S[j][2] - mn1);
                float p3 = __expf(S[j][3] - mn1);
                rs0 += p0 + p1; rs1 += p2 + p3;
                ap[jj * 2]     = pack_h2(p0, p1);
                ap[jj * 2 + 1] = pack_h2(p2, p3);
            }
            #pragma unroll
            for (int nb = 0; nb < 4; nb++) {
                uint32_t vh[4];
                // trans ldsm from V row-major [kv][d]
                uint32_t ro = (p * 16 + arow_l) * 144 + (nb * 16 + akc_h) * 2;
                ldsm4t(vh, sb + 18432 + ro);
                mma_fp16(O[nb*2],   ap, vh[0], vh[1]);
                mma_fp16(O[nb*2+1], ap, vh[2], vh[3]);
            }
        }
        rs0 += __shfl_xor_sync(0xffffffffu, rs0, 1);
        rs0 += __shfl_xor_sync(0xffffffffu, rs0, 2);
        rs1 += __shfl_xor_sync(0xffffffffu, rs1, 1);
        rs1 += __shfl_xor_sync(0xffffffffu, rs1, 2);
        li0 = li0 * sc0 + rs0; mi0 = mn0;
        li1 = li1 * sc1 + rs1; mi1 = mn1;
    }

    float inv0 = frcp(li0), inv1 = frcp(li1);
    #pragma unroll
    for (int j = 0; j < 8; j++) {
        int dj = hh * 64 + j * 8 + cb;
        uint32_t hp, lp;
        split_pair(O[j][0] * inv0, O[j][1] * inv0, hp, lp);
        size_t i0 = (size_t)(b * L_ + qrow0) * E_ + dj;
        *(uint32_t*)(g_ath + i0) = hp;
        *(uint32_t*)(g_atl + i0) = lp;
        split_pair(O[j][2] * inv1, O[j][3] * inv1, hp, lp);
        size_t i1 = (size_t)(b * L_ + qrow1) * E_ + dj;
        *(uint32_t*)(g_ath + i1) = hp;
        *(uint32_t*)(g_atl + i1) = lp;
    }
}

// ---------------------------------------------------------------------------
extern "C" void kernel_launch(void* const* d_in, const int* in_sizes, int n_in,
                              void* d_out, int out_size) {
    const float* x    = (const float*)d_in[0];
    const int*   mask = (const int*)d_in[1];
    const float* Wqkv = (const float*)d_in[2];
    const float* bqkv = (const float*)d_in[3];
    const float* Wout = (const float*)d_in[4];
    const float* bout = (const float*)d_in[5];
    float* out = (float*)d_out;

    cudaFuncSetAttribute(gemm_bf16, cudaFuncAttributeMaxDynamicSharedMemorySize, GEMM_SMEM);
    cudaFuncSetAttribute(yat_attn_mma, cudaFuncAttributeMaxDynamicSharedMemorySize, ATTN_SMEM);

    __nv_bfloat16 *xh, *xl, *wqh, *wql, *woh, *wol, *ath, *atl;
    cudaGetSymbolAddress((void**)&xh, g_xh);   cudaGetSymbolAddress((void**)&xl, g_xl);
    cudaGetSymbolAddress((void**)&wqh, g_wqh); cudaGetSymbolAddress((void**)&wql, g_wql);
    cudaGetSymbolAddress((void**)&woh, g_woh); cudaGetSymbolAddress((void**)&wol, g_wol);
    cudaGetSymbolAddress((void**)&ath, g_ath); cudaGetSymbolAddress((void**)&atl, g_atl);

    preproc<<<PRE_CONV + PRE_WQ + PRE_WO, 256>>>(x, Wqkv, Wout);

    dim3 g1(NQKV / 128, M_ / 128);   // 18 x 32
    gemm_bf16<<<g1, 256, GEMM_SMEM>>>(xh, xl, wqh, wql, bqkv, nullptr, 0);

    sqnorm_kernel<<<BH_ * L_ / 256, 256>>>();

    dim3 g2(L_ / 128, BH_);          // 16 x 24
    yat_attn_mma<<<g2, 256, ATTN_SMEM>>>(mask);

    dim3 g3(E_ / 128, M_ / 128);     // 6 x 32
    gemm_bf16<<<g3, 256, GEMM_SMEM>>>(ath, atl, woh, wol, bout, out, 1);
}

// round 16
// speedup vs baseline: 1.0164x; 1.0164x over previous
#include <cuda_runtime.h>
#include <cuda_bf16.h>
#include <cuda_fp16.h>
#include <math.h>
#include <float.h>
#include <stdint.h>

#define B_   2
#define L_   2048
#define E_   768
#define H_   12
#define D_   64
#define M_   (B_*L_)
#define NQKV (3*E_)
#define KDIM 768
#define BH_  (B_*H_)
#define LN2F 0.6931471805599453f

// Scratch (__device__ globals per allocation rules)
__device__ __nv_bfloat16 g_xh[M_*KDIM],    g_xl[M_*KDIM];
__device__ __nv_bfloat16 g_wqh[NQKV*KDIM], g_wql[NQKV*KDIM];
__device__ __nv_bfloat16 g_woh[E_*KDIM],   g_wol[E_*KDIM];
__device__ __nv_bfloat16 g_qh[BH_*L_*D_],  g_ql[BH_*L_*D_];
__device__ __nv_bfloat16 g_kh[BH_*L_*D_],  g_kl[BH_*L_*D_];
__device__ __half        g_vh[BH_*D_*L_];                    // [bh][d][l], fp16
__device__ __nv_bfloat16 g_ath[M_*E_],     g_atl[M_*E_];
__device__ float g_qsq[BH_*L_], g_ksq[BH_*L_];               // BOTH pre-scaled by ln2; ksq has +eps

__device__ __forceinline__ uint32_t smem_u32(const void* p) {
    uint32_t a;
    asm("{ .reg .u64 t; cvta.to.shared.u64 t, %1; cvt.u32.u64 %0, t; }" : "=r"(a) : "l"(p));
    return a;
}
__device__ __forceinline__ float frcp(float x) {
    float r;
    asm("rcp.approx.f32 %0, %1;" : "=f"(r) : "f"(x));
    return r;
}
__device__ __forceinline__ float fex2(float x) {
    float r;
    asm("ex2.approx.f32 %0, %1;" : "=f"(r) : "f"(x));
    return r;
}
__device__ __forceinline__ void mma_bf16(float c[4], const uint32_t a[4],
                                         uint32_t b0, uint32_t b1) {
    asm volatile(
        "mma.sync.aligned.m16n8k16.row.col.f32.bf16.bf16.f32 "
        "{%0,%1,%2,%3}, {%4,%5,%6,%7}, {%8,%9}, {%0,%1,%2,%3};"
        : "+f"(c[0]), "+f"(c[1]), "+f"(c[2]), "+f"(c[3])
        : "r"(a[0]), "r"(a[1]), "r"(a[2]), "r"(a[3]), "r"(b0), "r"(b1));
}
__device__ __forceinline__ void mma_fp16(float c[4], const uint32_t a[4],
                                         uint32_t b0, uint32_t b1) {
    asm volatile(
        "mma.sync.aligned.m16n8k16.row.col.f32.f16.f16.f32 "
        "{%0,%1,%2,%3}, {%4,%5,%6,%7}, {%8,%9}, {%0,%1,%2,%3};"
        : "+f"(c[0]), "+f"(c[1]), "+f"(c[2]), "+f"(c[3])
        : "r"(a[0]), "r"(a[1]), "r"(a[2]), "r"(a[3]), "r"(b0), "r"(b1));
}
__device__ __forceinline__ void ldsm4(uint32_t r[4], uint32_t addr) {
    asm volatile("ldmatrix.sync.aligned.m8n8.x4.shared.b16 {%0,%1,%2,%3}, [%4];"
                 : "=r"(r[0]), "=r"(r[1]), "=r"(r[2]), "=r"(r[3]) : "r"(addr));
}
__device__ __forceinline__ void cpasync16(uint32_t dst, const void* src) {
    size_t g = __cvta_generic_to_global(src);
    asm volatile("cp.async.ca.shared.global [%0], [%1], 16;" :: "r"(dst), "l"(g));
}
#define CP_COMMIT() asm volatile("cp.async.commit_group;" ::: "memory")
#define CP_WAIT0()  asm volatile("cp.async.wait_group 0;" ::: "memory")

__device__ __forceinline__ void split_pair(float x0, float x1,
                                           uint32_t& hp, uint32_t& lp) {
    __nv_bfloat16 h0 = __float2bfloat16(x0), h1 = __float2bfloat16(x1);
    hp = ((uint32_t)__bfloat16_as_ushort(h1) << 16) | __bfloat16_as_ushort(h0);
    __nv_bfloat16 l0 = __float2bfloat16(x0 - __bfloat162float(h0));
    __nv_bfloat16 l1 = __float2bfloat16(x1 - __bfloat162float(h1));
    lp = ((uint32_t)__bfloat16_as_ushort(l1) << 16) | __bfloat16_as_ushort(l0);
}
__device__ __forceinline__ uint32_t pack_h2(float x0, float x1) {
    __half2 h = __floats2half2_rn(x0, x1);
    return *reinterpret_cast<uint32_t*>(&h);
}

// ---------------- merged preprocessing (one launch) ----------------
#define PRE_CONV 3072
#define PRE_WQ   1728
#define PRE_WO   576

__global__ __launch_bounds__(256) void preproc(const float* __restrict__ x,
                                               const float* __restrict__ Wqkv,
                                               const float* __restrict__ Wout) {
    int bid = blockIdx.x;
    if (bid < PRE_CONV) {
        int i = (bid * 256 + threadIdx.x) * 4;
        float4 v = *(const float4*)(x + i);
        uint32_t h0, l0, h1, l1;
        split_pair(v.x, v.y, h0, l0);
        split_pair(v.z, v.w, h1, l1);
        *reinterpret_cast<uint2*>(g_xh + i) = make_uint2(h0, h1);
        *reinterpret_cast<uint2*>(g_xl + i) = make_uint2(l0, l1);
        return;
    }
    __shared__ float tile[32][33];
    const float* in;
    __nv_bfloat16 *oh, *ol;
    int N, idx;
    if (bid < PRE_CONV + PRE_WQ) {
        idx = bid - PRE_CONV; N = NQKV; in = Wqkv; oh = g_wqh; ol = g_wql;
    } else {
        idx = bid - PRE_CONV - PRE_WQ; N = E_; in = Wout; oh = g_woh; ol = g_wol;
    }
    int nblk = N / 32;
    int n0 = (idx % nblk) * 32, k0 = (idx / nblk) * 32;
    int tx = threadIdx.x & 31, ty = threadIdx.x >> 5;
    #pragma unroll
    for (int i = 0; i < 32; i += 8)
        tile[ty + i][tx] = in[(size_t)(k0 + ty + i) * N + n0 + tx];
    __syncthreads();
    #pragma unroll
    for (int i = 0; i < 32; i += 8) {
        float v = tile[tx][ty + i];
        __nv_bfloat16 h = __float2bfloat16(v);
        size_t o = (size_t)(n0 + ty + i) * KDIM + k0 + tx;
        oh[o] = h;
        ol[o] = __float2bfloat16(v - __bfloat162float(h));
    }
}

__global__ __launch_bounds__(256) void sqnorm_kernel() {
    int i = blockIdx.x * 256 + threadIdx.x;
    const uint32_t* qh = (const uint32_t*)g_qh + (size_t)i * 32;
    const uint32_t* ql = (const uint32_t*)g_ql + (size_t)i * 32;
    const uint32_t* kh = (const uint32_t*)g_kh + (size_t)i * 32;
    const uint32_t* kl = (const uint32_t*)g_kl + (size_t)i * 32;
    float sq = 0.f, sk = 0.f;
    #pragma unroll
    for (int j = 0; j < 32; j++) {
        uint32_t uh = qh[j], ul = ql[j];
        float2 fh = __bfloat1622float2(*reinterpret_cast<__nv_bfloat162*>(&uh));
        float2 fl = __bfloat1622float2(*reinterpret_cast<__nv_bfloat162*>(&ul));
        float v0 = fh.x + fl.x, v1 = fh.y + fl.y;
        sq += v0 * v0 + v1 * v1;
        uh = kh[j]; ul = kl[j];
        fh = __bfloat1622float2(*reinterpret_cast<__nv_bfloat162*>(&uh));
        fl = __bfloat1622float2(*reinterpret_cast<__nv_bfloat162*>(&ul));
        v0 = fh.x + fl.x; v1 = fh.y + fl.y;
        sk += v0 * v0 + v1 * v1;
    }
    g_qsq[i] = sq * LN2F;              // pre-scaled by ln2
    g_ksq[i] = (sk + 1e-6f) * LN2F;    // pre-scaled by ln2, eps folded
}

// ---------------- bf16-split tensor-core GEMM (R14 proven) ----------------
#define GBUF 73728
#define GEMM_SMEM (2*GBUF)

__global__ __launch_bounds__(256, 1) void gemm_bf16(
    const __nv_bfloat16* __restrict__ Ah, const __nv_bfloat16* __restrict__ Al,
    const __nv_bfloat16* __restrict__ Bh, const __nv_bfloat16* __restrict__ Bl,
    const float* __restrict__ bias, float* __restrict__ Cout, int mode) {
    extern __shared__ char smraw[];
    uint32_t sbase = smem_u32(smraw);
    const int t = threadIdx.x, lane = t & 31, w = t >> 5;
    const int wm = w >> 2, wn = w & 3;
    const int m0 = blockIdx.y * 128, n0 = blockIdx.x * 128;

    float acc[4][4][4];
    #pragma unroll
    for (int a = 0; a < 4; a++)
        #pragma unroll
        for (int b = 0; b < 4; b++)
            #pragma unroll
            for (int c = 0; c < 4; c++) acc[a][b][c] = 0.f;

    auto stage = [&](int c, int buf) {
        uint32_t sb = sbase + buf * GBUF;
        #pragma unroll
        for (int i = 0; i < 4; i++) {
            int idx = t + i * 256;
            int row = idx >> 3, c16 = idx & 7;
            size_t go = ((size_t)(m0 + row) * KDIM + c * 64 + c16 * 8) * 2;
            uint32_t so = row * 144 + c16 * 16;
            cpasync16(sb + so,         (const char*)Ah + go);
            cpasync16(sb + 18432 + so, (const char*)Al + go);
            size_t bo = ((size_t)(n0 + row) * KDIM + c * 64 + c16 * 8) * 2;
            cpasync16(sb + 36864 + so, (const char*)Bh + bo);
            cpasync16(sb + 55296 + so, (const char*)Bl + bo);
        }
    };

    stage(0, 0); CP_COMMIT();
    const int arow_l = ((lane >> 3) & 1) * 8 + (lane & 7);
    const int akc_h  = ((lane >> 4) & 1) * 8;
    const int brow_l = ((lane >> 4) & 1) * 8 + (lane & 7);
    const int bkc_h  = ((lane >> 3) & 1) * 8;

    for (int c = 0; c < 12; c++) {
        CP_WAIT0();
        __syncthreads();
        if (c < 11) { stage(c + 1, (c + 1) & 1); CP_COMMIT(); }
        uint32_t sb = sbase + (c & 1) * GBUF;
        #pragma unroll
        for (int ks = 0; ks < 4; ks++) {
            uint32_t aH[4][4], aL[4][4], bH[4][2], bL[4][2];
            #pragma unroll
            for (int mi = 0; mi < 4; mi++) {
                uint32_t ro = (wm * 64 + mi * 16 + arow_l) * 144 + (ks * 16 + akc_h) * 2;
                ldsm4(aH[mi], sb + ro);
                ldsm4(aL[mi], sb + 18432 + ro);
            }
            #pragma unroll
            for (int np = 0; np < 2; np++) {
                uint32_t r[4];
                uint32_t ro = (wn * 32 + np * 16 + brow_l) * 144 + (ks * 16 + bkc_h) * 2;
                ldsm4(r, sb + 36864 + ro);
                bH[np*2][0] = r[0]; bH[np*2][1] = r[1];
                bH[np*2+1][0] = r[2]; bH[np*2+1][1] = r[3];
                ldsm4(r, sb + 55296 + ro);
                bL[np*2][0] = r[0]; bL[np*2][1] = r[1];
                bL[np*2+1][0] = r[2]; bL[np*2+1][1] = r[3];
            }
            #pragma unroll
            for (int mi = 0; mi < 4; mi++)
                #pragma unroll
                for (int ni = 0; ni < 4; ni++) {
                    mma_bf16(acc[mi][ni], aH[mi], bH[ni][0], bH[ni][1]);
                    mma_bf16(acc[mi][ni], aH[mi], bL[ni][0], bL[ni][1]);
                    mma_bf16(acc[mi][ni], aL[mi], bH[ni][0], bH[ni][1]);
                }
        }
    }

    const int cb = (lane & 3) * 2;
    #pragma unroll
    for (int mi = 0; mi < 4; mi++) {
        int r0 = m0 + wm * 64 + mi * 16 + (lane >> 2);
        #pragma unroll
        for (int ni = 0; ni < 4; ni++) {
            int ncol = n0 + wn * 32 + ni * 8 + cb;
            float b0 = bias[ncol], b1 = bias[ncol + 1];
            float v[2][2] = {{acc[mi][ni][0] + b0, acc[mi][ni][1] + b1},
                             {acc[mi][ni][2] + b0, acc[mi][ni][3] + b1}};
            if (mode == 1) {
                *(float2*)(Cout + (size_t)r0 * E_ + ncol)       = make_float2(v[0][0], v[0][1]);
                *(float2*)(Cout + (size_t)(r0 + 8) * E_ + ncol) = make_float2(v[1][0], v[1][1]);
            } else {
                int s = ncol / E_;
                int rem = ncol - s * E_;
                int hh = rem >> 6, dd = rem & 63;
                #pragma unroll
                for (int rr = 0; rr < 2; rr++) {
                    int row = r0 + rr * 8;
                    int bb = row >> 11, l = row & (L_ - 1);
                    int bh = bb * H_ + hh;
                    if (s < 2) {
                        uint32_t hp, lp;
                        split_pair(v[rr][0], v[rr][1], hp, lp);
                        size_t idx = ((size_t)bh * L_ + l) * D_ + dd;
                        *(uint32_t*)((s ? g_kh : g_qh) + idx) = hp;
                        *(uint32_t*)((s ? g_kl : g_ql) + idx) = lp;
                    } else {
                        #pragma unroll
                        for (int e = 0; e < 2; e++) {
                            size_t ia = ((size_t)bh * D_ + dd + e) * L_ + l;
                            g_vh[ia] = __float2half_rn(v[rr][e]);
                        }
                    }
                }
            }
        }
    }
}

// ---------------- fused Yat attention: log2-space softmax, rescale skip ----------------
#define AQB   36864
#define ABUF2 28160
#define ATTN_SMEM (AQB + 2*ABUF2)   // 93184

__global__ __launch_bounds__(256, 2) void yat_attn_mma(const int* __restrict__ mask) {
    extern __shared__ char smraw[];
    uint32_t sbase = smem_u32(smraw);
    const int t = threadIdx.x, lane = t & 31, w = t >> 5;
    const int bh = blockIdx.y, b = bh / H_, hh = bh - b * H_;
    const int qt0 = blockIdx.x * 128;
    const int cb = (lane & 3) * 2;
    const int qrow0 = qt0 + w * 16 + (lane >> 2);
    const int qrow1 = qrow0 + 8;

    const int arow_l = ((lane >> 3) & 1) * 8 + (lane & 7);
    const int akc_h  = ((lane >> 4) & 1) * 8;
    const int krow_l = ((lane >> 4) & 1) * 8 + (lane & 7);
    const int kkc_h  = ((lane >> 3) & 1) * 8;

    // Stage Q tile (hi/lo) into smem once
    #pragma unroll
    for (int i = 0; i < 4; i++) {
        int idx = t + i * 256;
        int row = idx >> 3, c16 = idx & 7;
        size_t go = ((size_t)(bh * L_ + qt0 + row) * 64 + c16 * 8) * 2;
        uint32_t so = row * 144 + c16 * 16;
        cpasync16(sbase + so,         (const char*)g_qh + go);
        cpasync16(sbase + 18432 + so, (const char*)g_ql + go);
    }

    // Staging constants (2 rows per thread)
    const int srow0 = t >> 3,   sc16 = t & 7;
    const int srow1 = srow0 + 32;
    const uint32_t so0 = srow0 * 144 + sc16 * 16;
    const uint32_t so1 = srow1 * 144 + sc16 * 16;
    const char* pKh0 = (const char*)g_kh + ((size_t)(bh * L_ + srow0) * 64 + sc16 * 8) * 2;
    const char* pKh1 = (const char*)g_kh + ((size_t)(bh * L_ + srow1) * 64 + sc16 * 8) * 2;
    const char* pKl0 = (const char*)g_kl + ((size_t)(bh * L_ + srow0) * 64 + sc16 * 8) * 2;
    const char* pKl1 = (const char*)g_kl + ((size_t)(bh * L_ + srow1) * 64 + sc16 * 8) * 2;
    const char* pV0  = (const char*)g_vh + ((size_t)(bh * 64 + srow0) * L_ + sc16 * 8) * 2;
    const char* pV1  = (const char*)g_vh + ((size_t)(bh * 64 + srow1) * L_ + sc16 * 8) * 2;

    auto stage = [&](int it, int buf) {
        uint32_t sb = sbase + AQB + buf * ABUF2;
        size_t ko = (size_t)it * 64 * 64 * 2;
        size_t vo = (size_t)it * 64 * 2;
        cpasync16(sb + so0,        pKh0 + ko);
        cpasync16(sb + so1,        pKh1 + ko);
        cpasync16(sb + 9216 + so0, pKl0 + ko);
        cpasync16(sb + 9216 + so1, pKl1 + ko);
        cpasync16(sb + 18432 + so0, pV0 + vo);
        cpasync16(sb + 18432 + so1, pV1 + vo);
        if (t < 64) {
            float2* kq = (float2*)(smraw + AQB + buf * ABUF2 + 27648);
            int kv = it * 64 + t;
            kq[t] = make_float2(g_ksq[bh * L_ + kv],               // ln2-scaled
                                mask[b * L_ + kv] ? 0.f : -FLT_MAX);
        }
    };

    stage(0, 0); CP_COMMIT();

    const float qs0 = g_qsq[bh * L_ + qrow0];   // ln2-scaled
    const float qs1 = g_qsq[bh * L_ + qrow1];

    float mi0 = -FLT_MAX, mi1 = -FLT_MAX, li0 = 0.f, li1 = 0.f;
    float O[8][4];
    #pragma unroll
    for (int i = 0; i < 8; i++)
        #pragma unroll
        for (int j = 0; j < 4; j++) O[i][j] = 0.f;

    for (int it = 0; it < 32; it++) {
        CP_WAIT0();
        __syncthreads();
        if (it < 31) { stage(it + 1, (it + 1) & 1); CP_COMMIT(); }
        uint32_t sb = sbase + AQB + (it & 1) * ABUF2;
        const float2* kqpen = (const float2*)(smraw + AQB + (it & 1) * ABUF2 + 27648);

        float S[8][4];
        #pragma unroll
        for (int i = 0; i < 8; i++)
            #pragma unroll
            for (int j = 0; j < 4; j++) S[i][j] = 0.f;
        float rm0 = -FLT_MAX, rm1 = -FLT_MAX;

        // Transform in log2 space: den' = ln2*(qs+ksq+eps) - 2ln2*d; s' = d^2/den' + pen
        auto transform_pair = [&](int pp) {
            #pragma unroll
            for (int jj = 0; jj < 2; jj++) {
                int j = 2 * pp + jj;
                float2 kp0 = kqpen[j * 8 + cb];
                float2 kp1 = kqpen[j * 8 + cb + 1];
                float d, sc;
                d = S[j][0];
                sc = fmaf(d * d, frcp(fmaf(-2.f * LN2F, d, qs0 + kp0.x)), kp0.y);
                S[j][0] = sc; rm0 = fmaxf(rm0, sc);
                d = S[j][1];
                sc = fmaf(d * d, frcp(fmaf(-2.f * LN2F, d, qs0 + kp1.x)), kp1.y);
                S[j][1] = sc; rm0 = fmaxf(rm0, sc);
                d = S[j][2];
                sc = fmaf(d * d, frcp(fmaf(-2.f * LN2F, d, qs1 + kp0.x)), kp0.y);
                S[j][2] = sc; rm1 = fmaxf(rm1, sc);
                d = S[j][3];
                sc = fmaf(d * d, frcp(fmaf(-2.f * LN2F, d, qs1 + kp1.x)), kp1.y);
                S[j][3] = sc; rm1 = fmaxf(rm1, sc);
            }
        };

        uint32_t qah[4][4], qal[4][4];
        #pragma unroll
        for (int ks = 0; ks < 4; ks++) {
            uint32_t qro = (w * 16 + arow_l) * 144 + (ks * 16 + akc_h) * 2;
            ldsm4(qah[ks], sbase + qro);
            ldsm4(qal[ks], sbase + 18432 + qro);
        }

        #pragma unroll
        for (int p = 0; p < 4; p++) {
            #pragma unroll
            for (int ks = 0; ks < 4; ks++) {
                uint32_t rh[4], rl[4];
                uint32_t ro = (p * 16 + krow_l) * 144 + (ks * 16 + kkc_h) * 2;
                ldsm4(rh, sb + ro);
                ldsm4(rl, sb + 9216 + ro);
                mma_bf16(S[2*p],   qah[ks], rh[0], rh[1]);
                mma_bf16(S[2*p],   qah[ks], rl[0], rl[1]);
                mma_bf16(S[2*p],   qal[ks], rh[0], rh[1]);
                mma_bf16(S[2*p+1], qah[ks], rh[2], rh[3]);
                mma_bf16(S[2*p+1], qah[ks], rl[2], rl[3]);
                mma_bf16(S[2*p+1], qal[ks], rh[2], rh[3]);
            }
            if (p > 0) transform_pair(p - 1);
        }
        transform_pair(3);

        rm0 = fmaxf(rm0, __shfl_xor_sync(0xffffffffu, rm0, 1));
        rm0 = fmaxf(rm0, __shfl_xor_sync(0xffffffffu, rm0, 2));
        rm1 = fmaxf(rm1, __shfl_xor_sync(0xffffffffu, rm1, 1));
        rm1 = fmaxf(rm1, __shfl_xor_sync(0xffffffffu, rm1, 2));

        float mn0 = fmaxf(mi0, rm0), mn1 = fmaxf(mi1, rm1);
        // Rescale O only when the running max actually changed (warp-uniform skip)
        bool stable = (mn0 == mi0) && (mn1 == mi1);
        if (!__all_sync(0xffffffffu, stable)) {
            float sc0 = fex2(mi0 - mn0), sc1 = fex2(mi1 - mn1);
            li0 *= sc0; li1 *= sc1;
            #pragma unroll
            for (int j = 0; j < 8; j++) {
                O[j][0] *= sc0; O[j][1] *= sc0;
                O[j][2] *= sc1; O[j][3] *= sc1;
            }
            mi0 = mn0; mi1 = mn1;
        }

        float rs0 = 0.f, rs1 = 0.f;
        uint32_t Pk[8][2];
        #pragma unroll
        for (int np = 0; np < 8; np++) {
            float p0 = fex2(S[np][0] - mi0);
            float p1 = fex2(S[np][1] - mi0);
            float p2 = fex2(S[np][2] - mi1);
            float p3 = fex2(S[np][3] - mi1);
            rs0 += p0 + p1; rs1 += p2 + p3;
            Pk[np][0] = pack_h2(p0, p1);
            Pk[np][1] = pack_h2(p2, p3);
        }
        rs0 += __shfl_xor_sync(0xffffffffu, rs0, 1);
        rs0 += __shfl_xor_sync(0xffffffffu, rs0, 2);
        rs1 += __shfl_xor_sync(0xffffffffu, rs1, 1);
        rs1 += __shfl_xor_sync(0xffffffffu, rs1, 2);
        li0 += rs0; li1 += rs1;

        // O += P @ V  (P fp16 packed, V single fp16)
        #pragma unroll
        for (int kk = 0; kk < 4; kk++) {
            uint32_t ap[4] = {Pk[2*kk][0], Pk[2*kk][1], Pk[2*kk+1][0], Pk[2*kk+1][1]};
            #pragma unroll
            for (int nb = 0; nb < 4; nb++) {
                uint32_t vh[4];
                uint32_t ro = (nb * 16 + krow_l) * 144 + (kk * 16 + kkc_h) * 2;
                ldsm4(vh, sb + 18432 + ro);
                mma_fp16(O[nb*2],   ap, vh[0], vh[1]);
                mma_fp16(O[nb*2+1], ap, vh[2], vh[3]);
            }
        }
    }

    float inv0 = frcp(li0), inv1 = frcp(li1);
    #pragma unroll
    for (int j = 0; j < 8; j++) {
        int dj = hh * 64 + j * 8 + cb;
        uint32_t hp, lp;
        split_pair(O[j][0] * inv0, O[j][1] * inv0, hp, lp);
        size_t i0 = (size_t)(b * L_ + qrow0) * E_ + dj;
        *(uint32_t*)(g_ath + i0) = hp;
        *(uint32_t*)(g_atl + i0) = lp;
        split_pair(O[j][2] * inv1, O[j][3] * inv1, hp, lp);
        size_t i1 = (size_t)(b * L_ + qrow1) * E_ + dj;
        *(uint32_t*)(g_ath + i1) = hp;
        *(uint32_t*)(g_atl + i1) = lp;
    }
}

// ---------------------------------------------------------------------------
extern "C" void kernel_launch(void* const* d_in, const int* in_sizes, int n_in,
                              void* d_out, int out_size) {
    const float* x    = (const float*)d_in[0];
    const int*   mask = (const int*)d_in[1];
    const float* Wqkv = (const float*)d_in[2];
    const float* bqkv = (const float*)d_in[3];
    const float* Wout = (const float*)d_in[4];
    const float* bout = (const float*)d_in[5];
    float* out = (float*)d_out;

    cudaFuncSetAttribute(gemm_bf16, cudaFuncAttributeMaxDynamicSharedMemorySize, GEMM_SMEM);
    cudaFuncSetAttribute(yat_attn_mma, cudaFuncAttributeMaxDynamicSharedMemorySize, ATTN_SMEM);

    __nv_bfloat16 *xh, *xl, *wqh, *wql, *woh, *wol, *ath, *atl;
    cudaGetSymbolAddress((void**)&xh, g_xh);   cudaGetSymbolAddress((void**)&xl, g_xl);
    cudaGetSymbolAddress((void**)&wqh, g_wqh); cudaGetSymbolAddress((void**)&wql, g_wql);
    cudaGetSymbolAddress((void**)&woh, g_woh); cudaGetSymbolAddress((void**)&wol, g_wol);
    cudaGetSymbolAddress((void**)&ath, g_ath); cudaGetSymbolAddress((void**)&atl, g_atl);

    preproc<<<PRE_CONV + PRE_WQ + PRE_WO, 256>>>(x, Wqkv, Wout);

    dim3 g1(NQKV / 128, M_ / 128);   // 18 x 32
    gemm_bf16<<<g1, 256, GEMM_SMEM>>>(xh, xl, wqh, wql, bqkv, nullptr, 0);

    sqnorm_kernel<<<BH_ * L_ / 256, 256>>>();

    dim3 g2(L_ / 128, BH_);          // 16 x 24
    yat_attn_mma<<<g2, 256, ATTN_SMEM>>>(mask);

    dim3 g3(E_ / 128, M_ / 128);     // 6 x 32
    gemm_bf16<<<g3, 256, GEMM_SMEM>>>(ath, atl, woh, wol, bout, out, 1);
}